// round 4
// baseline (speedup 1.0000x reference)
#include <cuda_runtime.h>
#include <math.h>
#include <stdint.h>

// Problem constants (fixed shapes for this benchmark)
#define NB    8192
#define ND    128
#define BM    128
#define BN    128
#define PAD   132          // smem row stride in floats (multiple of 4 for float4 alignment)
#define ONE_EPS (1.0f - 1e-5f)

// Scratch (static device globals; no allocation allowed)
__device__ float g_sim[(size_t)NB * NB];   // 256 MB similarity matrix
__device__ int   g_minpos[NB];             // ordered-int min positive sim per row
__device__ int   g_maxneg[NB];             // ordered-int max negative sim per row
__device__ int   g_lab[NB];                // labels as int32
__device__ float g_rowloss[NB];

// Monotone float <-> int mapping for atomicMin/Max on floats
__device__ __forceinline__ int f2o(float f) {
    int i = __float_as_int(f);
    return (i >= 0) ? i : (i ^ 0x7FFFFFFF);
}
__device__ __forceinline__ float o2f(int i) {
    return __int_as_float((i >= 0) ? i : (i ^ 0x7FFFFFFF));
}

__global__ void init_kernel(const int* __restrict__ lab32) {
    int i = blockIdx.x * blockDim.x + threadIdx.x;
    if (i < NB) {
        g_lab[i]    = lab32[i];
        g_minpos[i] = f2o(__int_as_float(0x7F800000));   // +inf
        g_maxneg[i] = f2o(__int_as_float(0xFF800000));   // -inf
    }
}

// Pass 1: symmetric tiled fp32 GEMM sim = F * F^T, fused stage-1 min/max mining.
// Grid: (NB/BN, NB/BM); blocks with bx < by exit (upper triangle only).
__global__ __launch_bounds__(256, 1)
void sim_kernel(const float* __restrict__ F) {
    const int a = blockIdx.y;          // row tile
    const int b = blockIdx.x;          // col tile
    if (b < a) return;
    const int r0 = a * BM, c0 = b * BN;

    extern __shared__ float sm[];
    float* As = sm;                    // [BM][PAD], row i, col k
    float* Bs = sm + BM * PAD;         // [BN][PAD], row j, col k

    __shared__ int sla[BM], slb[BN];
    __shared__ int scmin[BN], scmax[BN];

    const int tid = threadIdx.x;
    const int tx = tid & 15;           // j-group
    const int ty = tid >> 4;           // i-group

    if (tid < BM) {
        sla[tid] = g_lab[r0 + tid];
        slb[tid] = g_lab[c0 + tid];
        scmin[tid] = f2o(__int_as_float(0x7F800000));
        scmax[tid] = f2o(__int_as_float(0xFF800000));
    }

    // Cooperative tile load: warp handles a full 128-float row per iteration (coalesced)
    {
        const int warp = tid >> 5, l = tid & 31;
        #pragma unroll
        for (int it = 0; it < 16; ++it) {
            int row = warp + 8 * it;
            float4 va = *(const float4*)(F + (size_t)(r0 + row) * ND + 4 * l);
            *(float4*)(As + row * PAD + 4 * l) = va;
            float4 vb = *(const float4*)(F + (size_t)(c0 + row) * ND + 4 * l);
            *(float4*)(Bs + row * PAD + 4 * l) = vb;
        }
    }
    __syncthreads();

    // 8x8 micro-tile per thread, strided mapping: i = ty + 16*ii, j = tx + 16*jj
    float acc[8][8];
    #pragma unroll
    for (int ii = 0; ii < 8; ++ii)
        #pragma unroll
        for (int jj = 0; jj < 8; ++jj) acc[ii][jj] = 0.0f;

    #pragma unroll 2
    for (int k4 = 0; k4 < ND / 4; ++k4) {
        float4 af[8], bf[8];
        #pragma unroll
        for (int ii = 0; ii < 8; ++ii)
            af[ii] = *(const float4*)(As + (ty + 16 * ii) * PAD + 4 * k4);
        #pragma unroll
        for (int jj = 0; jj < 8; ++jj)
            bf[jj] = *(const float4*)(Bs + (tx + 16 * jj) * PAD + 4 * k4);
        #pragma unroll
        for (int ii = 0; ii < 8; ++ii)
            #pragma unroll
            for (int jj = 0; jj < 8; ++jj) {
                acc[ii][jj] += af[ii].x * bf[jj].x;
                acc[ii][jj] += af[ii].y * bf[jj].y;
                acc[ii][jj] += af[ii].z * bf[jj].z;
                acc[ii][jj] += af[ii].w * bf[jj].w;
            }
    }
    __syncthreads();

    int li[8], lj[8];
    #pragma unroll
    for (int ii = 0; ii < 8; ++ii) li[ii] = sla[ty + 16 * ii];
    #pragma unroll
    for (int jj = 0; jj < 8; ++jj) lj[jj] = slb[tx + 16 * jj];

    const float PINF = __int_as_float(0x7F800000);
    const float NINF = __int_as_float(0xFF800000);

    // Row-direction stage-1 mining: reduce over jj, then across tx via shuffle
    #pragma unroll
    for (int ii = 0; ii < 8; ++ii) {
        float pmin = PINF, nmax = NINF;
        #pragma unroll
        for (int jj = 0; jj < 8; ++jj) {
            float s = acc[ii][jj];
            if (li[ii] == lj[jj]) {
                if (s < ONE_EPS) pmin = fminf(pmin, s);
            } else {
                nmax = fmaxf(nmax, s);
            }
        }
        #pragma unroll
        for (int m = 1; m < 16; m <<= 1) {
            pmin = fminf(pmin, __shfl_xor_sync(0xFFFFFFFFu, pmin, m));
            nmax = fmaxf(nmax, __shfl_xor_sync(0xFFFFFFFFu, nmax, m));
        }
        if (tx == 0) {
            atomicMin(&g_minpos[r0 + ty + 16 * ii], f2o(pmin));
            atomicMax(&g_maxneg[r0 + ty + 16 * ii], f2o(nmax));
        }
    }

    // Col-direction mining (rows c0+j see these sims too); skip on diagonal tiles
    if (a != b) {
        #pragma unroll
        for (int jj = 0; jj < 8; ++jj) {
            float pmin = PINF, nmax = NINF;
            #pragma unroll
            for (int ii = 0; ii < 8; ++ii) {
                float s = acc[ii][jj];
                if (li[ii] == lj[jj]) {
                    if (s < ONE_EPS) pmin = fminf(pmin, s);
                } else {
                    nmax = fmaxf(nmax, s);
                }
            }
            atomicMin(&scmin[tx + 16 * jj], f2o(pmin));
            atomicMax(&scmax[tx + 16 * jj], f2o(nmax));
        }
        __syncthreads();
        if (tid < BN) {
            atomicMin(&g_minpos[c0 + tid], scmin[tid]);
            atomicMax(&g_maxneg[c0 + tid], scmax[tid]);
        }
    }

    // Write C tile (coalesced: lanes tx contiguous in j)
    #pragma unroll
    for (int ii = 0; ii < 8; ++ii)
        #pragma unroll
        for (int jj = 0; jj < 8; ++jj)
            g_sim[(size_t)(r0 + ty + 16 * ii) * NB + (c0 + tx + 16 * jj)] = acc[ii][jj];

    // Write C^T tile via smem round-trip (keeps global stores coalesced)
    if (a != b) {
        float* Ts = As;  // reuse [128][PAD]
        __syncthreads();
        #pragma unroll
        for (int ii = 0; ii < 8; ++ii)
            #pragma unroll
            for (int jj = 0; jj < 8; ++jj)
                Ts[(tx + 16 * jj) * PAD + (ty + 16 * ii)] = acc[ii][jj];
        __syncthreads();
        #pragma unroll
        for (int ii = 0; ii < 8; ++ii)
            #pragma unroll
            for (int jj = 0; jj < 8; ++jj)
                g_sim[(size_t)(c0 + ty + 16 * ii) * NB + (r0 + tx + 16 * jj)] =
                    Ts[(ty + 16 * ii) * PAD + (tx + 16 * jj)];
    }
}

// Pass 2: one block per row — stage-2 masked exp sums + row loss
__global__ __launch_bounds__(256)
void rowloss_kernel() {
    const int i = blockIdx.x;
    const int tid = threadIdx.x;
    const int li = g_lab[i];
    const float minpos = o2f(g_minpos[i]);
    const float maxneg = o2f(g_maxneg[i]);
    const bool has_pos = (minpos < 3.0e38f);
    const bool has_neg = (maxneg > -3.0e38f);

    float posS = 0.0f, negS = 0.0f;
    int posC = 0, negC = 0;

    const float4* row = (const float4*)(g_sim + (size_t)i * NB);
    for (int t = tid; t < NB / 4; t += 256) {
        float4 v = row[t];
        int j0 = 4 * t;
        float sv[4] = {v.x, v.y, v.z, v.w};
        #pragma unroll
        for (int c = 0; c < 4; ++c) {
            float s = sv[c];
            int lj = g_lab[j0 + c];
            if (lj == li) {
                if (s < ONE_EPS && (s - 0.1f) < maxneg) {
                    posS += __expf(-2.0f * (s - 0.5f));
                    posC++;
                }
            } else {
                if ((s + 0.1f) > minpos) {
                    negS += __expf(40.0f * (s - 0.5f));
                    negC++;
                }
            }
        }
    }

    // deterministic reduction: shuffle within warp, smem across warps
    #pragma unroll
    for (int m = 16; m > 0; m >>= 1) {
        posS += __shfl_xor_sync(0xFFFFFFFFu, posS, m);
        negS += __shfl_xor_sync(0xFFFFFFFFu, negS, m);
        posC += __shfl_xor_sync(0xFFFFFFFFu, posC, m);
        negC += __shfl_xor_sync(0xFFFFFFFFu, negC, m);
    }
    __shared__ float sp[8], sn[8];
    __shared__ int   cp[8], cn[8];
    const int warp = tid >> 5;
    if ((tid & 31) == 0) { sp[warp] = posS; sn[warp] = negS; cp[warp] = posC; cn[warp] = negC; }
    __syncthreads();
    if (tid == 0) {
        float tS = 0.0f, tN = 0.0f; int tPC = 0, tNC = 0;
        #pragma unroll
        for (int w = 0; w < 8; ++w) { tS += sp[w]; tN += sn[w]; tPC += cp[w]; tNC += cn[w]; }
        bool valid = has_pos && has_neg && (tPC > 0) && (tNC > 0);
        float rl = valid ? (log1pf(tS) * 0.5f + log1pf(tN) * 0.025f) : 0.0f;
        g_rowloss[i] = rl;
    }
}

// Pass 3: deterministic final reduction
__global__ __launch_bounds__(256)
void final_kernel(float* __restrict__ out) {
    __shared__ float sdata[256];
    const int tid = threadIdx.x;
    float s = 0.0f;
    for (int i = tid; i < NB; i += 256) s += g_rowloss[i];
    sdata[tid] = s;
    __syncthreads();
    for (int step = 128; step > 0; step >>= 1) {
        if (tid < step) sdata[tid] += sdata[tid + step];
        __syncthreads();
    }
    if (tid == 0) out[0] = sdata[0] * (1.0f / (float)NB);
}

extern "C" void kernel_launch(void* const* d_in, const int* in_sizes, int n_in,
                              void* d_out, int out_size) {
    const float* F = (const float*)d_in[0];
    const int* lab = (const int*)d_in[1];
    float* out = (float*)d_out;

    const int smem_bytes = 2 * BM * PAD * (int)sizeof(float);  // 135168
    cudaFuncSetAttribute(sim_kernel, cudaFuncAttributeMaxDynamicSharedMemorySize, smem_bytes);

    init_kernel<<<(NB + 255) / 256, 256>>>(lab);
    dim3 grid(NB / BN, NB / BM);
    sim_kernel<<<grid, 256, smem_bytes>>>(F);
    rowloss_kernel<<<NB, 256>>>();
    final_kernel<<<1, 256>>>(out);
}

// round 9
// speedup vs baseline: 1.0810x; 1.0810x over previous
#include <cuda_runtime.h>
#include <cuda_bf16.h>
#include <math.h>
#include <stdint.h>

// Problem constants
#define NB    8192
#define ND    128
#define ONE_EPS (1.0f - 1e-5f)
#define PADC  129      // staging row stride in floats (129 % 32 == 1 -> conflict-free)
#define SMP   136      // operand row stride in bf16 elems (272 B -> conflict-free ldmatrix)

// Scratch (static device globals; no allocation allowed)
__device__ float         g_sim[(size_t)NB * NB];  // 256 MB similarity matrix
__device__ __nv_bfloat16 g_fhi[NB * ND];          // bf16 hi part of feats
__device__ __nv_bfloat16 g_flo[NB * ND];          // bf16 lo part of feats
__device__ int   g_minpos[NB];
__device__ int   g_maxneg[NB];
__device__ int   g_lab[NB];
__device__ float g_rowloss[NB];

// ordered-int <-> float for atomic min/max (deterministic)
__device__ __forceinline__ int f2o(float f) { int i = __float_as_int(f); return (i >= 0) ? i : (i ^ 0x7FFFFFFF); }
__device__ __forceinline__ float o2f(int i) { return __int_as_float((i >= 0) ? i : (i ^ 0x7FFFFFFF)); }

__device__ __forceinline__ uint32_t smem_u32(const void* p) {
    uint32_t a;
    asm("{ .reg .u64 t; cvta.to.shared.u64 t, %1; cvt.u32.u64 %0, t; }" : "=r"(a) : "l"(p));
    return a;
}
__device__ __forceinline__ void ldsm_x4(uint32_t addr, uint32_t& r0, uint32_t& r1, uint32_t& r2, uint32_t& r3) {
    asm volatile("ldmatrix.sync.aligned.m8n8.x4.shared.b16 {%0,%1,%2,%3}, [%4];"
                 : "=r"(r0), "=r"(r1), "=r"(r2), "=r"(r3) : "r"(addr));
}
__device__ __forceinline__ void ldsm_x2(uint32_t addr, uint32_t& r0, uint32_t& r1) {
    asm volatile("ldmatrix.sync.aligned.m8n8.x2.shared.b16 {%0,%1}, [%2];"
                 : "=r"(r0), "=r"(r1) : "r"(addr));
}
__device__ __forceinline__ void mma16816(float* c, const uint32_t* a, const uint32_t* b) {
    asm volatile("mma.sync.aligned.m16n8k16.row.col.f32.bf16.bf16.f32 "
                 "{%0,%1,%2,%3}, {%4,%5,%6,%7}, {%8,%9}, {%0,%1,%2,%3};"
                 : "+f"(c[0]), "+f"(c[1]), "+f"(c[2]), "+f"(c[3])
                 : "r"(a[0]), "r"(a[1]), "r"(a[2]), "r"(a[3]), "r"(b[0]), "r"(b[1]));
}

// ---------------- init: labels, min/max init, bf16 hi/lo split ----------------
__global__ void init_kernel(const float* __restrict__ F, const int* __restrict__ lab32) {
    int idx = blockIdx.x * blockDim.x + threadIdx.x;
    if (idx < NB * ND) {
        float v = F[idx];
        __nv_bfloat16 hi = __float2bfloat16(v);
        float r = v - __bfloat162float(hi);
        g_fhi[idx] = hi;
        g_flo[idx] = __float2bfloat16(r);
    }
    if (idx < NB) {
        g_lab[idx]    = lab32[idx];
        g_minpos[idx] = f2o(__int_as_float(0x7F800000));
        g_maxneg[idx] = f2o(__int_as_float(0xFF800000));
    }
}

// smem layout (dynamic), byte offsets
#define OFF_A_HI 0
#define OFF_A_LO 34816
#define OFF_B_HI 69632
#define OFF_B_LO 104448
#define OFF_TS   139264
#define SMEM_TOT (139264 + 128 * PADC * 4)   // 205312

// ---------------- pass 1: bf16-split mma.sync Gram tiles + stage-1 mining + sim store ----------------
__global__ __launch_bounds__(256, 1)
void sim_kernel() {
    const int a = blockIdx.y, b = blockIdx.x;
    if (b < a) return;
    const int r0 = a * 128, c0 = b * 128;

    extern __shared__ char smem[];
    const uint32_t sbase = smem_u32(smem);
    float* Ts = (float*)(smem + OFF_TS);

    __shared__ int sla[128], slb[128];

    const int tid = threadIdx.x;
    const int lane = tid & 31, wid = tid >> 5;
    const int wm = wid & 1, wn = wid >> 1;     // warp tile: rows wm*64, cols wn*32

    if (tid < 128) { sla[tid] = g_lab[r0 + tid]; slb[tid] = g_lab[c0 + tid]; }

    // Load operand tiles (bf16, pre-split) into padded smem rows (272 B stride)
    for (int t = tid; t < 2048; t += 256) {
        int row = t >> 4;
        int cg  = t & 15;                       // 8 bf16 (16 B) chunks
        uint32_t dst = (uint32_t)(row * (SMP * 2) + cg * 16);
        size_t srcA = (size_t)(r0 + row) * ND + cg * 8;
        size_t srcB = (size_t)(c0 + row) * ND + cg * 8;
        *(uint4*)(smem + OFF_A_HI + dst) = *(const uint4*)(g_fhi + srcA);
        *(uint4*)(smem + OFF_A_LO + dst) = *(const uint4*)(g_flo + srcA);
        *(uint4*)(smem + OFF_B_HI + dst) = *(const uint4*)(g_fhi + srcB);
        *(uint4*)(smem + OFF_B_LO + dst) = *(const uint4*)(g_flo + srcB);
    }
    __syncthreads();

    // Per-thread ldmatrix base offsets (bytes)
    const int arow = lane & 15;                 // lanes 0-15: rows, 16-31: rows at k+8
    const int acol = (lane >> 4) << 3;
    const uint32_t a_off0 = (uint32_t)(((wm * 64 + arow) * SMP + acol) * 2);
    const int brow = lane & 7;                  // x2 uses lanes 0-15
    const int bcol = ((lane >> 3) & 1) << 3;
    const uint32_t b_off0 = (uint32_t)(((wn * 32 + brow) * SMP + bcol) * 2);

    float c[4][4][4];
    #pragma unroll
    for (int mi = 0; mi < 4; ++mi)
        #pragma unroll
        for (int ni = 0; ni < 4; ++ni)
            #pragma unroll
            for (int k = 0; k < 4; ++k) c[mi][ni][k] = 0.0f;

    // K loop: 8 steps of k16; accumulate hihi + hilo + lohi + lolo
    #pragma unroll 1
    for (int ks = 0; ks < 8; ++ks) {
        uint32_t ahi[4][4], alo[4][4], bhi[4][2], blo[4][2];
        const uint32_t ka = a_off0 + ks * 32;
        const uint32_t kb = b_off0 + ks * 32;
        #pragma unroll
        for (int mi = 0; mi < 4; ++mi) {
            ldsm_x4(sbase + OFF_A_HI + ka + mi * (16 * SMP * 2), ahi[mi][0], ahi[mi][1], ahi[mi][2], ahi[mi][3]);
            ldsm_x4(sbase + OFF_A_LO + ka + mi * (16 * SMP * 2), alo[mi][0], alo[mi][1], alo[mi][2], alo[mi][3]);
        }
        #pragma unroll
        for (int ni = 0; ni < 4; ++ni) {
            ldsm_x2(sbase + OFF_B_HI + kb + ni * (8 * SMP * 2), bhi[ni][0], bhi[ni][1]);
            ldsm_x2(sbase + OFF_B_LO + kb + ni * (8 * SMP * 2), blo[ni][0], blo[ni][1]);
        }
        #pragma unroll
        for (int mi = 0; mi < 4; ++mi)
            #pragma unroll
            for (int ni = 0; ni < 4; ++ni) {
                mma16816(c[mi][ni], ahi[mi], bhi[ni]);
                mma16816(c[mi][ni], ahi[mi], blo[ni]);
                mma16816(c[mi][ni], alo[mi], bhi[ni]);
                mma16816(c[mi][ni], alo[mi], blo[ni]);
            }
    }

    // Stage C into padded smem
    #pragma unroll
    for (int mi = 0; mi < 4; ++mi)
        #pragma unroll
        for (int ni = 0; ni < 4; ++ni) {
            int r   = wm * 64 + mi * 16 + (lane >> 2);
            int col = wn * 32 + ni * 8 + (lane & 3) * 2;
            Ts[r * PADC + col]           = c[mi][ni][0];
            Ts[r * PADC + col + 1]       = c[mi][ni][1];
            Ts[(r + 8) * PADC + col]     = c[mi][ni][2];
            Ts[(r + 8) * PADC + col + 1] = c[mi][ni][3];
        }
    __syncthreads();

    const float PINF = __int_as_float(0x7F800000);
    const float NINF = __int_as_float(0xFF800000);

    // Row-direction stage-1 mining: thread tid (<128) owns tile row tid
    if (tid < 128) {
        const int li = sla[tid];
        float pmin = PINF, nmax = NINF;
        const float* rp = Ts + tid * PADC;
        #pragma unroll 4
        for (int cc = 0; cc < 128; ++cc) {
            float s = rp[cc];
            if (li == slb[cc]) { if (s < ONE_EPS) pmin = fminf(pmin, s); }
            else               { nmax = fmaxf(nmax, s); }
        }
        atomicMin(&g_minpos[r0 + tid], f2o(pmin));
        atomicMax(&g_maxneg[r0 + tid], f2o(nmax));
    }

    // Col-direction mining (off-diagonal tiles): thread tid (<128) owns tile col tid
    if (a != b && tid < 128) {
        const int lj = slb[tid];
        float pmin = PINF, nmax = NINF;
        #pragma unroll 4
        for (int r = 0; r < 128; ++r) {
            float s = Ts[r * PADC + tid];
            if (lj == sla[r]) { if (s < ONE_EPS) pmin = fminf(pmin, s); }
            else              { nmax = fmaxf(nmax, s); }
        }
        atomicMin(&g_minpos[c0 + tid], f2o(pmin));
        atomicMax(&g_maxneg[c0 + tid], f2o(nmax));
    }
    __syncthreads();

    // Coalesced stores: direct tile and (off-diagonal) transposed tile, 256 threads
    {
        const int col = tid & 127, rs = tid >> 7;
        #pragma unroll 4
        for (int r = rs; r < 128; r += 2)
            g_sim[(size_t)(r0 + r) * NB + (c0 + col)] = Ts[r * PADC + col];
        if (a != b) {
            #pragma unroll 4
            for (int r = rs; r < 128; r += 2)
                g_sim[(size_t)(c0 + r) * NB + (r0 + col)] = Ts[col * PADC + r];
        }
    }
}

// ---------------- pass 2: stage-2 masked exp sums + row loss ----------------
__global__ __launch_bounds__(256)
void rowloss_kernel() {
    const int i = blockIdx.x;
    const int tid = threadIdx.x;

    __shared__ int slab[NB];   // 32 KB label cache
    for (int t = tid; t < NB / 4; t += 256)
        ((int4*)slab)[t] = ((const int4*)g_lab)[t];
    __syncthreads();

    const int li = slab[i];
    const float minpos = o2f(g_minpos[i]);
    const float maxneg = o2f(g_maxneg[i]);
    const bool has_pos = (minpos < 3.0e38f);
    const bool has_neg = (maxneg > -3.0e38f);

    float posS = 0.0f, negS = 0.0f;
    int posC = 0, negC = 0;

    const float4* row = (const float4*)(g_sim + (size_t)i * NB);
    for (int t = tid; t < NB / 4; t += 256) {
        float4 v = row[t];
        int j0 = 4 * t;
        float sv[4] = {v.x, v.y, v.z, v.w};
        #pragma unroll
        for (int cc = 0; cc < 4; ++cc) {
            float s = sv[cc];
            int lj = slab[j0 + cc];
            if (lj == li) {
                if (s < ONE_EPS && (s - 0.1f) < maxneg) {
                    posS += __expf(-2.0f * (s - 0.5f));
                    posC++;
                }
            } else {
                if ((s + 0.1f) > minpos) {
                    negS += __expf(40.0f * (s - 0.5f));
                    negC++;
                }
            }
        }
    }

    #pragma unroll
    for (int m = 16; m > 0; m >>= 1) {
        posS += __shfl_xor_sync(0xFFFFFFFFu, posS, m);
        negS += __shfl_xor_sync(0xFFFFFFFFu, negS, m);
        posC += __shfl_xor_sync(0xFFFFFFFFu, posC, m);
        negC += __shfl_xor_sync(0xFFFFFFFFu, negC, m);
    }
    __shared__ float sp[8], sn[8];
    __shared__ int   cp[8], cn[8];
    const int warp = tid >> 5;
    if ((tid & 31) == 0) { sp[warp] = posS; sn[warp] = negS; cp[warp] = posC; cn[warp] = negC; }
    __syncthreads();
    if (tid == 0) {
        float tS = 0.0f, tN = 0.0f; int tPC = 0, tNC = 0;
        #pragma unroll
        for (int w = 0; w < 8; ++w) { tS += sp[w]; tN += sn[w]; tPC += cp[w]; tNC += cn[w]; }
        bool valid = has_pos && has_neg && (tPC > 0) && (tNC > 0);
        g_rowloss[i] = valid ? (log1pf(tS) * 0.5f + log1pf(tN) * 0.025f) : 0.0f;
    }
}

// ---------------- pass 3: final reduction ----------------
__global__ __launch_bounds__(256)
void final_kernel(float* __restrict__ out) {
    __shared__ float sdata[256];
    const int tid = threadIdx.x;
    float s = 0.0f;
    for (int i = tid; i < NB; i += 256) s += g_rowloss[i];
    sdata[tid] = s;
    __syncthreads();
    for (int step = 128; step > 0; step >>= 1) {
        if (tid < step) sdata[tid] += sdata[tid + step];
        __syncthreads();
    }
    if (tid == 0) out[0] = sdata[0] * (1.0f / (float)NB);
}

extern "C" void kernel_launch(void* const* d_in, const int* in_sizes, int n_in,
                              void* d_out, int out_size) {
    const float* F = (const float*)d_in[0];
    const int* lab = (const int*)d_in[1];
    float* out = (float*)d_out;

    cudaFuncSetAttribute(sim_kernel, cudaFuncAttributeMaxDynamicSharedMemorySize, SMEM_TOT);

    init_kernel<<<(NB * ND + 255) / 256, 256>>>(F, lab);
    dim3 grid(NB / 128, NB / 128);
    sim_kernel<<<grid, 256, SMEM_TOT>>>();
    rowloss_kernel<<<NB, 256>>>();
    final_kernel<<<1, 256>>>(out);
}

// round 10
// speedup vs baseline: 1.2913x; 1.1945x over previous
#include <cuda_runtime.h>
#include <cuda_bf16.h>
#include <math.h>
#include <stdint.h>

// Problem constants
#define NB    8192
#define ND    128
#define ONE_EPS (1.0f - 1e-5f)
#define SMP   136      // operand row stride in bf16 elems (272 B -> conflict-free ldmatrix)

// Scratch (static device globals; no allocation allowed)
__device__ __nv_bfloat16 g_fhi[NB * ND];          // bf16 hi part of feats
__device__ __nv_bfloat16 g_flo[NB * ND];          // bf16 lo part of feats
__device__ int   g_minpos[NB];                    // ordered-int min positive sim
__device__ int   g_maxneg[NB];                    // ordered-int max negative sim
__device__ int   g_lab[NB];
__device__ float g_posS[NB];
__device__ float g_negS[NB];
__device__ float g_rowloss[NB];

// ordered-int <-> float for atomic min/max (deterministic)
__device__ __forceinline__ int f2o(float f) { int i = __float_as_int(f); return (i >= 0) ? i : (i ^ 0x7FFFFFFF); }
__device__ __forceinline__ float o2f(int i) { return __int_as_float((i >= 0) ? i : (i ^ 0x7FFFFFFF)); }

__device__ __forceinline__ uint32_t smem_u32(const void* p) {
    uint32_t a;
    asm("{ .reg .u64 t; cvta.to.shared.u64 t, %1; cvt.u32.u64 %0, t; }" : "=r"(a) : "l"(p));
    return a;
}
__device__ __forceinline__ void ldsm_x4(uint32_t addr, uint32_t& r0, uint32_t& r1, uint32_t& r2, uint32_t& r3) {
    asm volatile("ldmatrix.sync.aligned.m8n8.x4.shared.b16 {%0,%1,%2,%3}, [%4];"
                 : "=r"(r0), "=r"(r1), "=r"(r2), "=r"(r3) : "r"(addr));
}
__device__ __forceinline__ void ldsm_x2(uint32_t addr, uint32_t& r0, uint32_t& r1) {
    asm volatile("ldmatrix.sync.aligned.m8n8.x2.shared.b16 {%0,%1}, [%2];"
                 : "=r"(r0), "=r"(r1) : "r"(addr));
}
__device__ __forceinline__ void mma16816(float* c, const uint32_t* a, const uint32_t* b) {
    asm volatile("mma.sync.aligned.m16n8k16.row.col.f32.bf16.bf16.f32 "
                 "{%0,%1,%2,%3}, {%4,%5,%6,%7}, {%8,%9}, {%0,%1,%2,%3};"
                 : "+f"(c[0]), "+f"(c[1]), "+f"(c[2]), "+f"(c[3])
                 : "r"(a[0]), "r"(a[1]), "r"(a[2]), "r"(a[3]), "r"(b[0]), "r"(b[1]));
}

// smem layout (dynamic), byte offsets: 4 operand tiles, 34816 B each
#define OFF_A_HI 0
#define OFF_A_LO 34816
#define OFF_B_HI 69632
#define OFF_B_LO 104448
#define SMEM_TOT 139264

// ---------------- init: labels, accum init, bf16 hi/lo split ----------------
__global__ void init_kernel(const float* __restrict__ F, const int* __restrict__ lab32) {
    int idx = blockIdx.x * blockDim.x + threadIdx.x;
    if (idx < NB * ND) {
        float v = F[idx];
        __nv_bfloat16 hi = __float2bfloat16(v);
        float r = v - __bfloat162float(hi);
        g_fhi[idx] = hi;
        g_flo[idx] = __float2bfloat16(r);
    }
    if (idx < NB) {
        g_lab[idx]    = lab32[idx];
        g_minpos[idx] = f2o(__int_as_float(0x7F800000));
        g_maxneg[idx] = f2o(__int_as_float(0xFF800000));
        g_posS[idx]   = 0.0f;
        g_negS[idx]   = 0.0f;
    }
}

// Shared tile GEMM: loads operands, syncs, computes C = Ahi*Bhi^T + Ahi*Blo^T + Alo*Bhi^T
// Fragment c[mi][ni][k]: row = wm*64+mi*16+(lane>>2)+(k>=2?8:0), col = wn*32+ni*8+(lane&3)*2+(k&1)
__device__ __forceinline__ void gemm_tile(float c[4][4][4], int r0, int c0,
                                          char* smem, uint32_t sbase,
                                          int tid, int lane, int wm, int wn) {
    for (int t = tid; t < 2048; t += 256) {
        int row = t >> 4, cg = t & 15;
        uint32_t dst = (uint32_t)(row * (SMP * 2) + cg * 16);
        size_t srcA = (size_t)(r0 + row) * ND + cg * 8;
        size_t srcB = (size_t)(c0 + row) * ND + cg * 8;
        *(uint4*)(smem + OFF_A_HI + dst) = *(const uint4*)(g_fhi + srcA);
        *(uint4*)(smem + OFF_A_LO + dst) = *(const uint4*)(g_flo + srcA);
        *(uint4*)(smem + OFF_B_HI + dst) = *(const uint4*)(g_fhi + srcB);
        *(uint4*)(smem + OFF_B_LO + dst) = *(const uint4*)(g_flo + srcB);
    }
    __syncthreads();

    const int arow = lane & 15;
    const int acol = (lane >> 4) << 3;
    const uint32_t a_off0 = (uint32_t)(((wm * 64 + arow) * SMP + acol) * 2);
    const int brow = lane & 7;
    const int bcol = ((lane >> 3) & 1) << 3;
    const uint32_t b_off0 = (uint32_t)(((wn * 32 + brow) * SMP + bcol) * 2);

    #pragma unroll
    for (int mi = 0; mi < 4; ++mi)
        #pragma unroll
        for (int ni = 0; ni < 4; ++ni)
            #pragma unroll
            for (int k = 0; k < 4; ++k) c[mi][ni][k] = 0.0f;

    #pragma unroll 1
    for (int ks = 0; ks < 8; ++ks) {
        uint32_t ahi[4][4], alo[4][4], bhi[4][2], blo[4][2];
        const uint32_t ka = a_off0 + ks * 32;
        const uint32_t kb = b_off0 + ks * 32;
        #pragma unroll
        for (int mi = 0; mi < 4; ++mi) {
            ldsm_x4(sbase + OFF_A_HI + ka + mi * (16 * SMP * 2), ahi[mi][0], ahi[mi][1], ahi[mi][2], ahi[mi][3]);
            ldsm_x4(sbase + OFF_A_LO + ka + mi * (16 * SMP * 2), alo[mi][0], alo[mi][1], alo[mi][2], alo[mi][3]);
        }
        #pragma unroll
        for (int ni = 0; ni < 4; ++ni) {
            ldsm_x2(sbase + OFF_B_HI + kb + ni * (8 * SMP * 2), bhi[ni][0], bhi[ni][1]);
            ldsm_x2(sbase + OFF_B_LO + kb + ni * (8 * SMP * 2), blo[ni][0], blo[ni][1]);
        }
        #pragma unroll
        for (int mi = 0; mi < 4; ++mi)
            #pragma unroll
            for (int ni = 0; ni < 4; ++ni) {
                mma16816(c[mi][ni], ahi[mi], bhi[ni]);
                mma16816(c[mi][ni], ahi[mi], blo[ni]);
                mma16816(c[mi][ni], alo[mi], bhi[ni]);
            }
    }
}

// ---------------- pass A: stage-1 mining (no sim store) ----------------
__global__ __launch_bounds__(256, 1)
void mine_kernel() {
    const int a = blockIdx.y, b = blockIdx.x;
    if (b < a) return;
    const int r0 = a * 128, c0 = b * 128;

    extern __shared__ char smem[];
    const uint32_t sbase = smem_u32(smem);
    __shared__ int sla[128], slb[128];
    __shared__ int srmin[128], srmax[128], scmin[128], scmax[128];

    const int tid = threadIdx.x;
    const int lane = tid & 31, wid = tid >> 5;
    const int wm = wid & 1, wn = wid >> 1;

    const int OMIN = f2o(__int_as_float(0x7F800000));
    const int OMAX = f2o(__int_as_float(0xFF800000));
    if (tid < 128) {
        sla[tid] = g_lab[r0 + tid]; slb[tid] = g_lab[c0 + tid];
        srmin[tid] = OMIN; srmax[tid] = OMAX;
        scmin[tid] = OMIN; scmax[tid] = OMAX;
    }

    float c[4][4][4];
    gemm_tile(c, r0, c0, smem, sbase, tid, lane, wm, wn);

    const int rbase = wm * 64 + (lane >> 2);
    const int cbase = wn * 32 + (lane & 3) * 2;
    int la[8], lc[8];
    #pragma unroll
    for (int mi = 0; mi < 4; ++mi)
        #pragma unroll
        for (int hb = 0; hb < 2; ++hb) la[mi * 2 + hb] = sla[rbase + mi * 16 + hb * 8];
    #pragma unroll
    for (int ni = 0; ni < 4; ++ni)
        #pragma unroll
        for (int lb = 0; lb < 2; ++lb) lc[ni * 2 + lb] = slb[cbase + ni * 8 + lb];

    const float PINF = __int_as_float(0x7F800000);
    const float NINF = __int_as_float(0xFF800000);
    float rmn[8], rmx[8], cmn[8], cmx[8];
    #pragma unroll
    for (int k = 0; k < 8; ++k) { rmn[k] = PINF; rmx[k] = NINF; cmn[k] = PINF; cmx[k] = NINF; }

    #pragma unroll
    for (int mi = 0; mi < 4; ++mi)
        #pragma unroll
        for (int ni = 0; ni < 4; ++ni)
            #pragma unroll
            for (int hb = 0; hb < 2; ++hb)
                #pragma unroll
                for (int lb = 0; lb < 2; ++lb) {
                    float s = c[mi][ni][hb * 2 + lb];
                    int ir = mi * 2 + hb, ic = ni * 2 + lb;
                    if (la[ir] == lc[ic]) {
                        if (s < ONE_EPS) { rmn[ir] = fminf(rmn[ir], s); cmn[ic] = fminf(cmn[ic], s); }
                    } else {
                        rmx[ir] = fmaxf(rmx[ir], s); cmx[ic] = fmaxf(cmx[ic], s);
                    }
                }

    // row reduce across lane bits 0-1 (cols), col reduce across lane bits 2-4 (rows)
    #pragma unroll
    for (int k = 0; k < 8; ++k) {
        rmn[k] = fminf(rmn[k], __shfl_xor_sync(0xFFFFFFFFu, rmn[k], 1));
        rmn[k] = fminf(rmn[k], __shfl_xor_sync(0xFFFFFFFFu, rmn[k], 2));
        rmx[k] = fmaxf(rmx[k], __shfl_xor_sync(0xFFFFFFFFu, rmx[k], 1));
        rmx[k] = fmaxf(rmx[k], __shfl_xor_sync(0xFFFFFFFFu, rmx[k], 2));
        cmn[k] = fminf(cmn[k], __shfl_xor_sync(0xFFFFFFFFu, cmn[k], 4));
        cmn[k] = fminf(cmn[k], __shfl_xor_sync(0xFFFFFFFFu, cmn[k], 8));
        cmn[k] = fminf(cmn[k], __shfl_xor_sync(0xFFFFFFFFu, cmn[k], 16));
        cmx[k] = fmaxf(cmx[k], __shfl_xor_sync(0xFFFFFFFFu, cmx[k], 4));
        cmx[k] = fmaxf(cmx[k], __shfl_xor_sync(0xFFFFFFFFu, cmx[k], 8));
        cmx[k] = fmaxf(cmx[k], __shfl_xor_sync(0xFFFFFFFFu, cmx[k], 16));
    }
    if ((lane & 3) == 0) {
        #pragma unroll
        for (int k = 0; k < 8; ++k) {
            int row = wm * 64 + (k >> 1) * 16 + (k & 1) * 8 + (lane >> 2);
            atomicMin(&srmin[row], f2o(rmn[k]));
            atomicMax(&srmax[row], f2o(rmx[k]));
        }
    }
    if (a != b && (lane >> 2) == 0) {
        #pragma unroll
        for (int k = 0; k < 8; ++k) {
            int col = wn * 32 + (k >> 1) * 8 + (k & 1) + (lane & 3) * 2;
            atomicMin(&scmin[col], f2o(cmn[k]));
            atomicMax(&scmax[col], f2o(cmx[k]));
        }
    }
    __syncthreads();
    if (tid < 128) {
        atomicMin(&g_minpos[r0 + tid], srmin[tid]);
        atomicMax(&g_maxneg[r0 + tid], srmax[tid]);
        if (a != b) {
            atomicMin(&g_minpos[c0 + tid], scmin[tid]);
            atomicMax(&g_maxneg[c0 + tid], scmax[tid]);
        }
    }
}

// ---------------- pass B: recompute tiles, stage-2 masked exp sums ----------------
__global__ __launch_bounds__(256, 1)
void loss_kernel() {
    const int a = blockIdx.y, b = blockIdx.x;
    if (b < a) return;
    const int r0 = a * 128, c0 = b * 128;

    extern __shared__ char smem[];
    const uint32_t sbase = smem_u32(smem);
    __shared__ int sla[128], slb[128];
    __shared__ float smpr[128], smnr[128], smpc[128], smnc[128];
    __shared__ float srp[128], srn[128], scp[128], scn[128];

    const int tid = threadIdx.x;
    const int lane = tid & 31, wid = tid >> 5;
    const int wm = wid & 1, wn = wid >> 1;

    if (tid < 128) {
        sla[tid] = g_lab[r0 + tid]; slb[tid] = g_lab[c0 + tid];
        smpr[tid] = o2f(g_minpos[r0 + tid]); smnr[tid] = o2f(g_maxneg[r0 + tid]);
        smpc[tid] = o2f(g_minpos[c0 + tid]); smnc[tid] = o2f(g_maxneg[c0 + tid]);
        srp[tid] = 0.0f; srn[tid] = 0.0f; scp[tid] = 0.0f; scn[tid] = 0.0f;
    }

    float c[4][4][4];
    gemm_tile(c, r0, c0, smem, sbase, tid, lane, wm, wn);

    const int rbase = wm * 64 + (lane >> 2);
    const int cbase = wn * 32 + (lane & 3) * 2;
    int la[8], lc[8];
    float mpr[8], mnr[8], mpc[8], mnc[8];
    #pragma unroll
    for (int mi = 0; mi < 4; ++mi)
        #pragma unroll
        for (int hb = 0; hb < 2; ++hb) {
            int r = rbase + mi * 16 + hb * 8;
            la[mi * 2 + hb] = sla[r]; mpr[mi * 2 + hb] = smpr[r]; mnr[mi * 2 + hb] = smnr[r];
        }
    #pragma unroll
    for (int ni = 0; ni < 4; ++ni)
        #pragma unroll
        for (int lb = 0; lb < 2; ++lb) {
            int cl = cbase + ni * 8 + lb;
            lc[ni * 2 + lb] = slb[cl]; mpc[ni * 2 + lb] = smpc[cl]; mnc[ni * 2 + lb] = smnc[cl];
        }

    float rp[8], rn[8], cp[8], cn[8];
    #pragma unroll
    for (int k = 0; k < 8; ++k) { rp[k] = 0.0f; rn[k] = 0.0f; cp[k] = 0.0f; cn[k] = 0.0f; }

    const bool offd = (a != b);
    #pragma unroll
    for (int mi = 0; mi < 4; ++mi)
        #pragma unroll
        for (int ni = 0; ni < 4; ++ni)
            #pragma unroll
            for (int hb = 0; hb < 2; ++hb)
                #pragma unroll
                for (int lb = 0; lb < 2; ++lb) {
                    float s = c[mi][ni][hb * 2 + lb];
                    int ir = mi * 2 + hb, ic = ni * 2 + lb;
                    bool same = (la[ir] == lc[ic]);
                    float arg = same ? (-2.0f * (s - 0.5f)) : (40.0f * (s - 0.5f));
                    float t = __expf(arg);
                    bool okp = same && (s < ONE_EPS);
                    rp[ir] += (okp  && (s - 0.1f) < mnr[ir]) ? t : 0.0f;
                    rn[ir] += (!same && (s + 0.1f) > mpr[ir]) ? t : 0.0f;
                    if (offd) {
                        cp[ic] += (okp  && (s - 0.1f) < mnc[ic]) ? t : 0.0f;
                        cn[ic] += (!same && (s + 0.1f) > mpc[ic]) ? t : 0.0f;
                    }
                }

    #pragma unroll
    for (int k = 0; k < 8; ++k) {
        rp[k] += __shfl_xor_sync(0xFFFFFFFFu, rp[k], 1);
        rp[k] += __shfl_xor_sync(0xFFFFFFFFu, rp[k], 2);
        rn[k] += __shfl_xor_sync(0xFFFFFFFFu, rn[k], 1);
        rn[k] += __shfl_xor_sync(0xFFFFFFFFu, rn[k], 2);
        cp[k] += __shfl_xor_sync(0xFFFFFFFFu, cp[k], 4);
        cp[k] += __shfl_xor_sync(0xFFFFFFFFu, cp[k], 8);
        cp[k] += __shfl_xor_sync(0xFFFFFFFFu, cp[k], 16);
        cn[k] += __shfl_xor_sync(0xFFFFFFFFu, cn[k], 4);
        cn[k] += __shfl_xor_sync(0xFFFFFFFFu, cn[k], 8);
        cn[k] += __shfl_xor_sync(0xFFFFFFFFu, cn[k], 16);
    }
    if ((lane & 3) == 0) {
        #pragma unroll
        for (int k = 0; k < 8; ++k) {
            int row = wm * 64 + (k >> 1) * 16 + (k & 1) * 8 + (lane >> 2);
            atomicAdd(&srp[row], rp[k]);
            atomicAdd(&srn[row], rn[k]);
        }
    }
    if (offd && (lane >> 2) == 0) {
        #pragma unroll
        for (int k = 0; k < 8; ++k) {
            int col = wn * 32 + (k >> 1) * 8 + (k & 1) + (lane & 3) * 2;
            atomicAdd(&scp[col], cp[k]);
            atomicAdd(&scn[col], cn[k]);
        }
    }
    __syncthreads();
    if (tid < 128) {
        atomicAdd(&g_posS[r0 + tid], srp[tid]);
        atomicAdd(&g_negS[r0 + tid], srn[tid]);
        if (offd) {
            atomicAdd(&g_posS[c0 + tid], scp[tid]);
            atomicAdd(&g_negS[c0 + tid], scn[tid]);
        }
    }
}

// ---------------- finalize: per-row loss ----------------
__global__ __launch_bounds__(256)
void rowfin_kernel() {
    int i = blockIdx.x * 256 + threadIdx.x;
    if (i >= NB) return;
    float minpos = o2f(g_minpos[i]);
    float maxneg = o2f(g_maxneg[i]);
    float pS = g_posS[i], nS = g_negS[i];
    bool valid = (minpos < 3.0e38f) && (maxneg > -3.0e38f) && (pS > 0.0f) && (nS > 0.0f);
    g_rowloss[i] = valid ? (log1pf(pS) * 0.5f + log1pf(nS) * 0.025f) : 0.0f;
}

// ---------------- final reduction ----------------
__global__ __launch_bounds__(256)
void final_kernel(float* __restrict__ out) {
    __shared__ float sdata[256];
    const int tid = threadIdx.x;
    float s = 0.0f;
    for (int i = tid; i < NB; i += 256) s += g_rowloss[i];
    sdata[tid] = s;
    __syncthreads();
    for (int step = 128; step > 0; step >>= 1) {
        if (tid < step) sdata[tid] += sdata[tid + step];
        __syncthreads();
    }
    if (tid == 0) out[0] = sdata[0] * (1.0f / (float)NB);
}

extern "C" void kernel_launch(void* const* d_in, const int* in_sizes, int n_in,
                              void* d_out, int out_size) {
    const float* F = (const float*)d_in[0];
    const int* lab = (const int*)d_in[1];
    float* out = (float*)d_out;

    cudaFuncSetAttribute(mine_kernel, cudaFuncAttributeMaxDynamicSharedMemorySize, SMEM_TOT);
    cudaFuncSetAttribute(loss_kernel, cudaFuncAttributeMaxDynamicSharedMemorySize, SMEM_TOT);

    init_kernel<<<(NB * ND + 255) / 256, 256>>>(F, lab);
    dim3 grid(NB / 128, NB / 128);
    mine_kernel<<<grid, 256, SMEM_TOT>>>();
    loss_kernel<<<grid, 256, SMEM_TOT>>>();
    rowfin_kernel<<<NB / 256, 256>>>();
    final_kernel<<<1, 256>>>(out);
}

// round 13
// speedup vs baseline: 1.3516x; 1.0467x over previous
#include <cuda_runtime.h>
#include <cuda_bf16.h>
#include <math.h>
#include <stdint.h>

// Problem constants
#define NB    8192
#define ND    128
#define ONE_EPS (1.0f - 1e-5f)

// Block tile: 256 rows x 128 cols, 8 warps (4 row-groups x 2 col-groups), warp tile 64x64
// smem operand layout: 256B row stride (128 bf16), 16-byte chunks, low-3-bit xor swizzle
#define OFF_A_HI 0u          // 256*256 = 65536
#define OFF_A_LO 65536u
#define OFF_B_HI 131072u     // 128*256 = 32768
#define OFF_B_LO 163840u
#define SMEM_TOT 196608

// Scratch (static device globals; no allocation allowed)
__device__ __nv_bfloat16 g_fhi[NB * ND];
__device__ __nv_bfloat16 g_flo[NB * ND];
__device__ int   g_minpos[NB];
__device__ int   g_maxneg[NB];
__device__ int   g_lab[NB];
__device__ float g_posS[NB];
__device__ float g_negS[NB];
__device__ float g_rowloss[NB];

__device__ __forceinline__ int f2o(float f) { int i = __float_as_int(f); return (i >= 0) ? i : (i ^ 0x7FFFFFFF); }
__device__ __forceinline__ float o2f(int i) { return __int_as_float((i >= 0) ? i : (i ^ 0x7FFFFFFF)); }

__device__ __forceinline__ uint32_t smem_u32(const void* p) {
    uint32_t a;
    asm("{ .reg .u64 t; cvta.to.shared.u64 t, %1; cvt.u32.u64 %0, t; }" : "=r"(a) : "l"(p));
    return a;
}
__device__ __forceinline__ void cp16(uint32_t dst, const void* src) {
    asm volatile("cp.async.cg.shared.global [%0], [%1], 16;" :: "r"(dst), "l"(src));
}
__device__ __forceinline__ void ldsm_x4(uint32_t addr, uint32_t& r0, uint32_t& r1, uint32_t& r2, uint32_t& r3) {
    asm volatile("ldmatrix.sync.aligned.m8n8.x4.shared.b16 {%0,%1,%2,%3}, [%4];"
                 : "=r"(r0), "=r"(r1), "=r"(r2), "=r"(r3) : "r"(addr));
}
__device__ __forceinline__ void ldsm_x2(uint32_t addr, uint32_t& r0, uint32_t& r1) {
    asm volatile("ldmatrix.sync.aligned.m8n8.x2.shared.b16 {%0,%1}, [%2];"
                 : "=r"(r0), "=r"(r1) : "r"(addr));
}
__device__ __forceinline__ void mma16816(float* c, const uint32_t* a, const uint32_t* b) {
    asm volatile("mma.sync.aligned.m16n8k16.row.col.f32.bf16.bf16.f32 "
                 "{%0,%1,%2,%3}, {%4,%5,%6,%7}, {%8,%9}, {%0,%1,%2,%3};"
                 : "+f"(c[0]), "+f"(c[1]), "+f"(c[2]), "+f"(c[3])
                 : "r"(a[0]), "r"(a[1]), "r"(a[2]), "r"(a[3]), "r"(b[0]), "r"(b[1]));
}

// ---------------- init ----------------
__global__ void init_kernel(const float* __restrict__ F, const int* __restrict__ lab32) {
    int idx = blockIdx.x * blockDim.x + threadIdx.x;
    if (idx < NB * ND) {
        float v = F[idx];
        __nv_bfloat16 hi = __float2bfloat16(v);
        float r = v - __bfloat162float(hi);
        g_fhi[idx] = hi;
        g_flo[idx] = __float2bfloat16(r);
    }
    if (idx < NB) {
        g_lab[idx]    = lab32[idx];
        g_minpos[idx] = f2o(__int_as_float(0x7F800000));
        g_maxneg[idx] = f2o(__int_as_float(0xFF800000));
        g_posS[idx]   = 0.0f;
        g_negS[idx]   = 0.0f;
    }
}

// Issue cp.async loads for k-half h (chunks 8h..8h+7), commit as one group.
// Row stride 256 B; chunk swizzle flips only low 3 bits (bit 3 = k-half preserved).
__device__ __forceinline__ void issue_loads(uint32_t sbase, int r0, int c0, int tid, int h) {
    for (int t = tid; t < 2048; t += 256) {            // A: 256 rows x 8 chunks
        int row = t >> 3, cg = (t & 7) + 8 * h;
        uint32_t dst = (uint32_t)(row * 256 + ((cg ^ (row & 7)) << 4));
        size_t src = (size_t)(r0 + row) * ND + cg * 8;
        cp16(sbase + OFF_A_HI + dst, g_fhi + src);
        cp16(sbase + OFF_A_LO + dst, g_flo + src);
    }
    for (int t = tid; t < 1024; t += 256) {            // B: 128 rows x 8 chunks
        int row = t >> 3, cg = (t & 7) + 8 * h;
        uint32_t dst = (uint32_t)(row * 256 + ((cg ^ (row & 7)) << 4));
        size_t src = (size_t)(c0 + row) * ND + cg * 8;
        cp16(sbase + OFF_B_HI + dst, g_fhi + src);
        cp16(sbase + OFF_B_LO + dst, g_flo + src);
    }
    asm volatile("cp.async.commit_group;" ::: "memory");
}

// Compute ksteps [ks0, ks1): C += Ahi*Bhi^T + Ahi*Blo^T + Alo*Bhi^T
__device__ __forceinline__ void compute_ks(float c[4][8][4], uint32_t sbase,
                                           int lane, int wm, int wn, int ks0, int ks1) {
    const int l7 = lane & 7;
    const uint32_t base_a = sbase + OFF_A_HI + (uint32_t)((wm * 64 + (lane & 15)) * 256);
    const uint32_t base_b = sbase + OFF_B_HI + (uint32_t)((wn * 64 + l7) * 256);
    #pragma unroll
    for (int ks = ks0; ks < ks1; ++ks) {
        uint32_t bhi[8][2], blo[8][2];
        int bch = ((lane >> 3) & 1) + 2 * ks;
        uint32_t bcs = (uint32_t)((bch ^ l7) << 4);
        #pragma unroll
        for (int ni = 0; ni < 8; ++ni) {
            uint32_t ad = base_b + ni * 2048 + bcs;     // 8 rows * 256 B
            ldsm_x2(ad, bhi[ni][0], bhi[ni][1]);
            ldsm_x2(ad + 32768, blo[ni][0], blo[ni][1]);
        }
        int ach = (lane >> 4) + 2 * ks;
        uint32_t acs = (uint32_t)((ach ^ l7) << 4);
        #pragma unroll
        for (int mi = 0; mi < 4; ++mi) {
            uint32_t ad = base_a + mi * 4096 + acs;     // 16 rows * 256 B
            uint32_t ahi[4], alo[4];
            ldsm_x4(ad, ahi[0], ahi[1], ahi[2], ahi[3]);
            ldsm_x4(ad + 65536, alo[0], alo[1], alo[2], alo[3]);
            #pragma unroll
            for (int ni = 0; ni < 8; ++ni) {
                mma16816(c[mi][ni], ahi, bhi[ni]);
                mma16816(c[mi][ni], ahi, blo[ni]);
                mma16816(c[mi][ni], alo, bhi[ni]);
            }
        }
    }
}

// Build 128-bit predicate (j>i) and same-label masks; bit index = ir*16+ic
__device__ __forceinline__ void build_masks(uint32_t pm[4], uint32_t sq[4],
                                            const int* sla, const int* slb,
                                            int r0, int c0, int lane, int wm, int wn) {
    #pragma unroll
    for (int w = 0; w < 4; ++w) { pm[w] = 0u; sq[w] = 0u; }
    #pragma unroll
    for (int ir = 0; ir < 8; ++ir) {
        int rl = wm * 64 + (ir >> 1) * 16 + (ir & 1) * 8 + (lane >> 2);
        int gi = r0 + rl, la = sla[rl];
        #pragma unroll
        for (int ic = 0; ic < 16; ++ic) {
            int cl = wn * 64 + (ic >> 1) * 8 + (ic & 1) + (lane & 3) * 2;
            int bit = ir * 16 + ic;
            if (c0 + cl > gi)    pm[bit >> 5] |= 1u << (bit & 31);
            if (la == slb[cl])   sq[bit >> 5] |= 1u << (bit & 31);
        }
    }
}

// ---------------- pass A: stage-1 mining ----------------
__global__ __launch_bounds__(256, 1)
void mine_kernel() {
    const int a = blockIdx.y, b = blockIdx.x;
    if (b < 2 * a) return;
    const int r0 = a * 256, c0 = b * 128;

    extern __shared__ char smem[];
    const uint32_t sbase = smem_u32(smem);
    __shared__ int sla[256], slb[128];
    __shared__ int srmin[256], srmax[256], scmin[128], scmax[128];

    const int tid = threadIdx.x;
    const int lane = tid & 31, wid = tid >> 5;
    const int wm = wid & 3, wn = wid >> 2;

    const int OMIN = f2o(__int_as_float(0x7F800000));
    const int OMAX = f2o(__int_as_float(0xFF800000));
    sla[tid] = g_lab[r0 + tid];
    srmin[tid] = OMIN; srmax[tid] = OMAX;
    if (tid < 128) { slb[tid] = g_lab[c0 + tid]; scmin[tid] = OMIN; scmax[tid] = OMAX; }

    issue_loads(sbase, r0, c0, tid, 0);
    issue_loads(sbase, r0, c0, tid, 1);

    float c[4][8][4];
    #pragma unroll
    for (int mi = 0; mi < 4; ++mi)
        #pragma unroll
        for (int ni = 0; ni < 8; ++ni)
            #pragma unroll
            for (int k = 0; k < 4; ++k) c[mi][ni][k] = 0.0f;

    asm volatile("cp.async.wait_group 1;" ::: "memory");
    __syncthreads();
    compute_ks(c, sbase, lane, wm, wn, 0, 4);
    asm volatile("cp.async.wait_group 0;" ::: "memory");
    __syncthreads();
    compute_ks(c, sbase, lane, wm, wn, 4, 8);

    uint32_t pm[4], sq[4];
    build_masks(pm, sq, sla, slb, r0, c0, lane, wm, wn);

    const float PINF = __int_as_float(0x7F800000);
    const float NINF = __int_as_float(0xFF800000);
    float rmn[8], rmx[8], cmn[16], cmx[16];
    #pragma unroll
    for (int k = 0; k < 8; ++k)  { rmn[k] = PINF; rmx[k] = NINF; }
    #pragma unroll
    for (int k = 0; k < 16; ++k) { cmn[k] = PINF; cmx[k] = NINF; }

    #pragma unroll
    for (int mi = 0; mi < 4; ++mi)
        #pragma unroll
        for (int ni = 0; ni < 8; ++ni)
            #pragma unroll
            for (int k = 0; k < 4; ++k) {
                int ir = mi * 2 + (k >> 1), ic = ni * 2 + (k & 1);
                int bit = ir * 16 + ic;
                bool p = (pm[bit >> 5] >> (bit & 31)) & 1u;
                bool se = (sq[bit >> 5] >> (bit & 31)) & 1u;
                float s = c[mi][ni][k];
                if (p) {
                    if (se) {
                        if (s < ONE_EPS) { rmn[ir] = fminf(rmn[ir], s); cmn[ic] = fminf(cmn[ic], s); }
                    } else {
                        rmx[ir] = fmaxf(rmx[ir], s); cmx[ic] = fmaxf(cmx[ic], s);
                    }
                }
            }

    #pragma unroll
    for (int k = 0; k < 8; ++k) {
        rmn[k] = fminf(rmn[k], __shfl_xor_sync(0xFFFFFFFFu, rmn[k], 1));
        rmn[k] = fminf(rmn[k], __shfl_xor_sync(0xFFFFFFFFu, rmn[k], 2));
        rmx[k] = fmaxf(rmx[k], __shfl_xor_sync(0xFFFFFFFFu, rmx[k], 1));
        rmx[k] = fmaxf(rmx[k], __shfl_xor_sync(0xFFFFFFFFu, rmx[k], 2));
    }
    #pragma unroll
    for (int k = 0; k < 16; ++k) {
        cmn[k] = fminf(cmn[k], __shfl_xor_sync(0xFFFFFFFFu, cmn[k], 4));
        cmn[k] = fminf(cmn[k], __shfl_xor_sync(0xFFFFFFFFu, cmn[k], 8));
        cmn[k] = fminf(cmn[k], __shfl_xor_sync(0xFFFFFFFFu, cmn[k], 16));
        cmx[k] = fmaxf(cmx[k], __shfl_xor_sync(0xFFFFFFFFu, cmx[k], 4));
        cmx[k] = fmaxf(cmx[k], __shfl_xor_sync(0xFFFFFFFFu, cmx[k], 8));
        cmx[k] = fmaxf(cmx[k], __shfl_xor_sync(0xFFFFFFFFu, cmx[k], 16));
    }
    if ((lane & 3) == 0) {
        #pragma unroll
        for (int ir = 0; ir < 8; ++ir) {
            int rl = wm * 64 + (ir >> 1) * 16 + (ir & 1) * 8 + (lane >> 2);
            atomicMin(&srmin[rl], f2o(rmn[ir]));
            atomicMax(&srmax[rl], f2o(rmx[ir]));
        }
    }
    if (lane < 4) {
        #pragma unroll
        for (int ic = 0; ic < 16; ++ic) {
            int cl = wn * 64 + (ic >> 1) * 8 + (ic & 1) + lane * 2;
            atomicMin(&scmin[cl], f2o(cmn[ic]));
            atomicMax(&scmax[cl], f2o(cmx[ic]));
        }
    }
    __syncthreads();
    atomicMin(&g_minpos[r0 + tid], srmin[tid]);
    atomicMax(&g_maxneg[r0 + tid], srmax[tid]);
    if (tid < 128) {
        atomicMin(&g_minpos[c0 + tid], scmin[tid]);
        atomicMax(&g_maxneg[c0 + tid], scmax[tid]);
    }
}

// ---------------- pass B: stage-2 masked exp sums ----------------
__global__ __launch_bounds__(256, 1)
void loss_kernel() {
    const int a = blockIdx.y, b = blockIdx.x;
    if (b < 2 * a) return;
    const int r0 = a * 256, c0 = b * 128;

    extern __shared__ char smem[];
    const uint32_t sbase = smem_u32(smem);
    __shared__ int sla[256], slb[128];
    __shared__ float s_mpr[256], s_mnr[256], s_mpc[128], s_mnc[128];
    __shared__ float srp[256], srn[256], scp[128], scn[128];

    const int tid = threadIdx.x;
    const int lane = tid & 31, wid = tid >> 5;
    const int wm = wid & 3, wn = wid >> 2;

    sla[tid] = g_lab[r0 + tid];
    s_mpr[tid] = o2f(g_minpos[r0 + tid]);
    s_mnr[tid] = o2f(g_maxneg[r0 + tid]);
    srp[tid] = 0.0f; srn[tid] = 0.0f;
    if (tid < 128) {
        slb[tid] = g_lab[c0 + tid];
        s_mpc[tid] = o2f(g_minpos[c0 + tid]);
        s_mnc[tid] = o2f(g_maxneg[c0 + tid]);
        scp[tid] = 0.0f; scn[tid] = 0.0f;
    }

    issue_loads(sbase, r0, c0, tid, 0);
    issue_loads(sbase, r0, c0, tid, 1);

    float c[4][8][4];
    #pragma unroll
    for (int mi = 0; mi < 4; ++mi)
        #pragma unroll
        for (int ni = 0; ni < 8; ++ni)
            #pragma unroll
            for (int k = 0; k < 4; ++k) c[mi][ni][k] = 0.0f;

    asm volatile("cp.async.wait_group 1;" ::: "memory");
    __syncthreads();
    compute_ks(c, sbase, lane, wm, wn, 0, 4);
    asm volatile("cp.async.wait_group 0;" ::: "memory");
    __syncthreads();
    compute_ks(c, sbase, lane, wm, wn, 4, 8);

    uint32_t pm[4], sq[4];
    build_masks(pm, sq, sla, slb, r0, c0, lane, wm, wn);

    float mpr[8], mnr[8];
    #pragma unroll
    for (int ir = 0; ir < 8; ++ir) {
        int rl = wm * 64 + (ir >> 1) * 16 + (ir & 1) * 8 + (lane >> 2);
        mpr[ir] = s_mpr[rl]; mnr[ir] = s_mnr[rl];
    }

    float rp[8], rn[8], cp[16], cn[16];
    #pragma unroll
    for (int k = 0; k < 8; ++k)  { rp[k] = 0.0f; rn[k] = 0.0f; }
    #pragma unroll
    for (int k = 0; k < 16; ++k) { cp[k] = 0.0f; cn[k] = 0.0f; }

    #pragma unroll
    for (int mi = 0; mi < 4; ++mi)
        #pragma unroll
        for (int ni = 0; ni < 8; ++ni)
            #pragma unroll
            for (int k = 0; k < 4; ++k) {
                int ir = mi * 2 + (k >> 1), ic = ni * 2 + (k & 1);
                int bit = ir * 16 + ic;
                bool p = (pm[bit >> 5] >> (bit & 31)) & 1u;
                bool se = (sq[bit >> 5] >> (bit & 31)) & 1u;
                float s = c[mi][ni][k];
                float arg = se ? (-2.0f * (s - 0.5f)) : (40.0f * (s - 0.5f));
                float t = __expf(arg);
                bool posok = p && se && (s < ONE_EPS);
                bool negok = p && !se;
                int cl = wn * 64 + (ic >> 1) * 8 + (ic & 1) + (lane & 3) * 2;
                if (posok && (s - 0.1f) < mnr[ir]) rp[ir] += t;
                if (negok && (s + 0.1f) > mpr[ir]) rn[ir] += t;
                if (posok && (s - 0.1f) < s_mnc[cl]) cp[ic] += t;
                if (negok && (s + 0.1f) > s_mpc[cl]) cn[ic] += t;
            }

    #pragma unroll
    for (int k = 0; k < 8; ++k) {
        rp[k] += __shfl_xor_sync(0xFFFFFFFFu, rp[k], 1);
        rp[k] += __shfl_xor_sync(0xFFFFFFFFu, rp[k], 2);
        rn[k] += __shfl_xor_sync(0xFFFFFFFFu, rn[k], 1);
        rn[k] += __shfl_xor_sync(0xFFFFFFFFu, rn[k], 2);
    }
    #pragma unroll
    for (int k = 0; k < 16; ++k) {
        cp[k] += __shfl_xor_sync(0xFFFFFFFFu, cp[k], 4);
        cp[k] += __shfl_xor_sync(0xFFFFFFFFu, cp[k], 8);
        cp[k] += __shfl_xor_sync(0xFFFFFFFFu, cp[k], 16);
        cn[k] += __shfl_xor_sync(0xFFFFFFFFu, cn[k], 4);
        cn[k] += __shfl_xor_sync(0xFFFFFFFFu, cn[k], 8);
        cn[k] += __shfl_xor_sync(0xFFFFFFFFu, cn[k], 16);
    }
    if ((lane & 3) == 0) {
        #pragma unroll
        for (int ir = 0; ir < 8; ++ir) {
            int rl = wm * 64 + (ir >> 1) * 16 + (ir & 1) * 8 + (lane >> 2);
            atomicAdd(&srp[rl], rp[ir]);
            atomicAdd(&srn[rl], rn[ir]);
        }
    }
    if (lane < 4) {
        #pragma unroll
        for (int ic = 0; ic < 16; ++ic) {
            int cl = wn * 64 + (ic >> 1) * 8 + (ic & 1) + lane * 2;
            atomicAdd(&scp[cl], cp[ic]);
            atomicAdd(&scn[cl], cn[ic]);
        }
    }
    __syncthreads();
    atomicAdd(&g_posS[r0 + tid], srp[tid]);
    atomicAdd(&g_negS[r0 + tid], srn[tid]);
    if (tid < 128) {
        atomicAdd(&g_posS[c0 + tid], scp[tid]);
        atomicAdd(&g_negS[c0 + tid], scn[tid]);
    }
}

// ---------------- finalize ----------------
__global__ __launch_bounds__(256)
void rowfin_kernel() {
    int i = blockIdx.x * 256 + threadIdx.x;
    if (i >= NB) return;
    float minpos = o2f(g_minpos[i]);
    float maxneg = o2f(g_maxneg[i]);
    float pS = g_posS[i], nS = g_negS[i];
    bool valid = (minpos < 3.0e38f) && (maxneg > -3.0e38f) && (pS > 0.0f) && (nS > 0.0f);
    g_rowloss[i] = valid ? (log1pf(pS) * 0.5f + log1pf(nS) * 0.025f) : 0.0f;
}

__global__ __launch_bounds__(256)
void final_kernel(float* __restrict__ out) {
    __shared__ float sdata[256];
    const int tid = threadIdx.x;
    float s = 0.0f;
    for (int i = tid; i < NB; i += 256) s += g_rowloss[i];
    sdata[tid] = s;
    __syncthreads();
    for (int step = 128; step > 0; step >>= 1) {
        if (tid < step) sdata[tid] += sdata[tid + step];
        __syncthreads();
    }
    if (tid == 0) out[0] = sdata[0] * (1.0f / (float)NB);
}

extern "C" void kernel_launch(void* const* d_in, const int* in_sizes, int n_in,
                              void* d_out, int out_size) {
    const float* F = (const float*)d_in[0];
    const int* lab = (const int*)d_in[1];
    float* out = (float*)d_out;

    cudaFuncSetAttribute(mine_kernel, cudaFuncAttributeMaxDynamicSharedMemorySize, SMEM_TOT);
    cudaFuncSetAttribute(loss_kernel, cudaFuncAttributeMaxDynamicSharedMemorySize, SMEM_TOT);

    init_kernel<<<(NB * ND + 255) / 256, 256>>>(F, lab);
    dim3 grid(64, 32);
    mine_kernel<<<grid, 256, SMEM_TOT>>>();
    loss_kernel<<<grid, 256, SMEM_TOT>>>();
    rowfin_kernel<<<NB / 256, 256>>>();
    final_kernel<<<1, 256>>>(out);
}